// round 1
// baseline (speedup 1.0000x reference)
#include <cuda_runtime.h>

#define N_CLI 100000
#define N_AGG 1000
#define NE    1600000
#define D     128
#define NLAY  3

// ---------------- scratch (device globals; no allocation allowed) ----------------
__device__ float g_xc0[N_CLI * D];
__device__ float g_xc1[N_CLI * D];
__device__ float g_xa0[N_AGG * D];
__device__ float g_xa1[N_AGG * D];
__device__ float g_Y[N_AGG * D];        // x_agg @ Wl_a2c[l]
__device__ float g_mean_a[N_AGG * D];
__device__ float g_Z[N_CLI * D];        // xc @ Wr_a2c[l] + b
__device__ int   g_csr_c2a[NE];
__device__ int   g_csr_a2c[NE];
__device__ int   g_off_c2a[N_AGG + 1];
__device__ int   g_off_a2c[N_CLI + 1];
__device__ int   g_cur_c2a[N_AGG];
__device__ int   g_cur_a2c[N_CLI];
__device__ int   g_cnt_c2a[N_AGG];
__device__ int   g_cnt_a2c[N_CLI];
__device__ float g_invc_a[N_AGG];
__device__ float g_invc_c[N_CLI];

// ---------------- CSR construction ----------------
__global__ void zero_int_kernel(int* p, int n) {
    int i = blockIdx.x * blockDim.x + threadIdx.x;
    if (i < n) p[i] = 0;
}

__global__ void hist_c2a_kernel(const int* __restrict__ dst, int* __restrict__ cnt) {
    __shared__ int h[N_AGG];
    for (int i = threadIdx.x; i < N_AGG; i += blockDim.x) h[i] = 0;
    __syncthreads();
    for (int e = blockIdx.x * blockDim.x + threadIdx.x; e < NE; e += gridDim.x * blockDim.x)
        atomicAdd(&h[dst[e]], 1);
    __syncthreads();
    for (int i = threadIdx.x; i < N_AGG; i += blockDim.x)
        if (h[i]) atomicAdd(&cnt[i], h[i]);
}

__global__ void hist_a2c_kernel(const int* __restrict__ dst, int* __restrict__ cnt) {
    int e = blockIdx.x * blockDim.x + threadIdx.x;
    if (e < NE) atomicAdd(&cnt[dst[e]], 1);
}

// single-block exclusive scan; also inits cursor array and inverse counts
__global__ void scan_init_kernel(const int* __restrict__ cnt, int* __restrict__ off,
                                 int* __restrict__ cur, float* __restrict__ invc, int n) {
    __shared__ int wsum[32];
    __shared__ int carry;
    int tid = threadIdx.x, lane = tid & 31, wid = tid >> 5;
    if (tid == 0) carry = 0;
    __syncthreads();
    for (int base = 0; base < n; base += 1024) {
        int i = base + tid;
        int v = (i < n) ? cnt[i] : 0;
        int x = v;
        #pragma unroll
        for (int o = 1; o < 32; o <<= 1) {
            int t = __shfl_up_sync(0xffffffffu, x, o);
            if (lane >= o) x += t;
        }
        if (lane == 31) wsum[wid] = x;
        __syncthreads();
        if (wid == 0) {
            int s = wsum[lane];
            #pragma unroll
            for (int o = 1; o < 32; o <<= 1) {
                int t = __shfl_up_sync(0xffffffffu, s, o);
                if (lane >= o) s += t;
            }
            wsum[lane] = s;
        }
        __syncthreads();
        int excl = x - v + (wid ? wsum[wid - 1] : 0) + carry;
        if (i < n) {
            off[i] = excl;
            cur[i] = excl;
            invc[i] = 1.0f / fmaxf((float)v, 1.0f);
        }
        __syncthreads();
        if (tid == 0) carry += wsum[31];
        __syncthreads();
    }
    if (threadIdx.x == 0) off[n] = carry;
}

__global__ void scatter_kernel(const int* __restrict__ src, const int* __restrict__ dst,
                               int* __restrict__ cur, int* __restrict__ csr) {
    int e = blockIdx.x * blockDim.x + threadIdx.x;
    if (e < NE) {
        int p = atomicAdd(&cur[dst[e]], 1);
        csr[p] = src[e];
    }
}

// ---------------- tiny GEMMs (N_AGG rows) ----------------
// C[r,:] = A[r,:] @ W     (one block per row, 128 threads)
__global__ void gemm_small_kernel(const float* __restrict__ A, const float* __restrict__ W,
                                  float* __restrict__ C) {
    __shared__ float row[D];
    int r = blockIdx.x, j = threadIdx.x;
    row[j] = A[r * D + j];
    __syncthreads();
    float acc = 0.f;
    #pragma unroll 8
    for (int k = 0; k < D; k++) acc += row[k] * W[k * D + j];
    C[r * D + j] = acc;
}

// xa_new = leaky(mean @ Wl + xa @ Wr + b)
__global__ void agg_update_kernel(const float* __restrict__ mean, const float* __restrict__ xa,
                                  const float* __restrict__ Wl, const float* __restrict__ Wr,
                                  const float* __restrict__ b, float* __restrict__ out) {
    __shared__ float rm[D], rx[D];
    int r = blockIdx.x, j = threadIdx.x;
    rm[j] = mean[r * D + j];
    rx[j] = xa[r * D + j];
    __syncthreads();
    float acc = b[j];
    #pragma unroll 4
    for (int k = 0; k < D; k++) acc += rm[k] * Wl[k * D + j] + rx[k] * Wr[k * D + j];
    out[r * D + j] = (acc >= 0.f) ? acc : 0.1f * acc;
}

// ---------------- c2a aggregation: mean of client rows per aggregator ----------------
__global__ void agg_c2a_kernel(const float* __restrict__ xc, const int* __restrict__ csr,
                               const int* __restrict__ off, const float* __restrict__ invc,
                               float* __restrict__ mean) {
    int a = blockIdx.x, j = threadIdx.x;
    int s = off[a], e = off[a + 1];
    float acc0 = 0.f, acc1 = 0.f, acc2 = 0.f, acc3 = 0.f;
    int i = s;
    for (; i + 4 <= e; i += 4) {
        int i0 = csr[i], i1 = csr[i + 1], i2 = csr[i + 2], i3 = csr[i + 3];
        acc0 += xc[i0 * D + j];
        acc1 += xc[i1 * D + j];
        acc2 += xc[i2 * D + j];
        acc3 += xc[i3 * D + j];
    }
    for (; i < e; i++) acc0 += xc[csr[i] * D + j];
    mean[a * D + j] = (acc0 + acc1 + acc2 + acc3) * invc[a];
}

// ---------------- big GEMM: Z = A(Mx128) @ W(128x128) + bias ----------------
#define BM 128
#define BN 128
#define BK 32

__global__ void __launch_bounds__(256)
big_gemm_kernel(const float* __restrict__ A, const float* __restrict__ W,
                const float* __restrict__ bias, float* __restrict__ C, int M) {
    __shared__ float As[BM][BK + 4];  // 128 x 36 floats (pad kills STS conflicts)
    __shared__ float Ws[BK][BN];
    int tid = threadIdx.x;
    int tn = tid & 15, tm = tid >> 4;
    int r0 = blockIdx.x * BM;
    float acc[8][8];
    #pragma unroll
    for (int i = 0; i < 8; i++)
        #pragma unroll
        for (int j = 0; j < 8; j++) acc[i][j] = 0.f;

    int rowA0 = tm * 4;  // rows rowA0..+3 and rowA0+64..+67
    int colB0 = tn * 4;  // cols colB0..+3 and colB0+64..+67

    for (int kc = 0; kc < D; kc += BK) {
        // A tile: 128 rows x 32 k
        {
            int r = tid >> 3;   // 0..31
            int kq = tid & 7;   // float4 index within BK
            #pragma unroll
            for (int p = 0; p < 4; p++) {
                int row = r0 + r + p * 32;
                int rc = (row < M) ? row : (M - 1);
                float4 v = *(const float4*)(&A[rc * D + kc + kq * 4]);
                *(float4*)(&As[r + p * 32][kq * 4]) = v;
            }
        }
        // W tile: 32 x 128
        {
            int n4 = tid & 31, kk = tid >> 5;
            #pragma unroll
            for (int p = 0; p < 4; p++) {
                int k = kk + p * 8;
                *(float4*)(&Ws[k][n4 * 4]) = *(const float4*)(&W[(kc + k) * D + n4 * 4]);
            }
        }
        __syncthreads();
        #pragma unroll
        for (int k = 0; k < BK; k++) {
            float a[8], b[8];
            #pragma unroll
            for (int i = 0; i < 4; i++) {
                a[i] = As[rowA0 + i][k];
                a[i + 4] = As[rowA0 + 64 + i][k];
            }
            float4 b0 = *(const float4*)(&Ws[k][colB0]);
            float4 b1 = *(const float4*)(&Ws[k][colB0 + 64]);
            b[0] = b0.x; b[1] = b0.y; b[2] = b0.z; b[3] = b0.w;
            b[4] = b1.x; b[5] = b1.y; b[6] = b1.z; b[7] = b1.w;
            #pragma unroll
            for (int i = 0; i < 8; i++)
                #pragma unroll
                for (int j = 0; j < 8; j++) acc[i][j] += a[i] * b[j];
        }
        __syncthreads();
    }
    #pragma unroll
    for (int i = 0; i < 8; i++) {
        int row = r0 + rowA0 + ((i < 4) ? i : (64 + i - 4));
        if (row < M) {
            #pragma unroll
            for (int jj = 0; jj < 2; jj++) {
                int col = colB0 + jj * 64;
                float4 o;
                o.x = acc[i][jj * 4 + 0] + bias[col + 0];
                o.y = acc[i][jj * 4 + 1] + bias[col + 1];
                o.z = acc[i][jj * 4 + 2] + bias[col + 2];
                o.w = acc[i][jj * 4 + 3] + bias[col + 3];
                *(float4*)(&C[row * D + col]) = o;
            }
        }
    }
}

// ---------------- client update: xc_new = leaky(gathersum(Y)/cnt + Z) ----------------
__global__ void client_update_kernel(const float* __restrict__ Zb, const float* __restrict__ Y,
                                     const int* __restrict__ csr, const int* __restrict__ off,
                                     const float* __restrict__ invc, float* __restrict__ out) {
    int warp = (blockIdx.x * blockDim.x + threadIdx.x) >> 5;
    int lane = threadIdx.x & 31;
    if (warp >= N_CLI) return;
    int s = off[warp], e = off[warp + 1];
    const float4* Y4 = (const float4*)Y;
    float4 acc = make_float4(0.f, 0.f, 0.f, 0.f);
    for (int base = s; base < e; base += 32) {
        int nv = min(32, e - base);
        int idx = (lane < nv) ? csr[base + lane] : 0;
        for (int t = 0; t < nv; t++) {
            int a = __shfl_sync(0xffffffffu, idx, t);
            float4 y = Y4[a * 32 + lane];
            acc.x += y.x; acc.y += y.y; acc.z += y.z; acc.w += y.w;
        }
    }
    float ic = invc[warp];
    float4 z = ((const float4*)Zb)[warp * 32 + lane];
    float4 v;
    v.x = z.x + acc.x * ic;
    v.y = z.y + acc.y * ic;
    v.z = z.z + acc.z * ic;
    v.w = z.w + acc.w * ic;
    v.x = (v.x >= 0.f) ? v.x : 0.1f * v.x;
    v.y = (v.y >= 0.f) ? v.y : 0.1f * v.y;
    v.z = (v.z >= 0.f) ? v.z : 0.1f * v.z;
    v.w = (v.w >= 0.f) ? v.w : 0.1f * v.w;
    ((float4*)out)[warp * 32 + lane] = v;
}

// ---------------- final linear ----------------
__global__ void final_kernel(const float* __restrict__ xc, const float* __restrict__ Wlin,
                             const float* __restrict__ blin, float* __restrict__ out) {
    int warp = (blockIdx.x * blockDim.x + threadIdx.x) >> 5;
    int lane = threadIdx.x & 31;
    if (warp >= N_CLI) return;
    float4 x = ((const float4*)xc)[warp * 32 + lane];
    float4 w = ((const float4*)Wlin)[lane];
    float s = x.x * w.x + x.y * w.y + x.z * w.z + x.w * w.w;
    #pragma unroll
    for (int o = 16; o; o >>= 1) s += __shfl_xor_sync(0xffffffffu, s, o);
    if (lane == 0) out[warp] = s + blin[0];
}

// ---------------- launch ----------------
extern "C" void kernel_launch(void* const* d_in, const int* in_sizes, int n_in,
                              void* d_out, int out_size) {
    (void)in_sizes; (void)n_in; (void)out_size;
    const float* x_clients = (const float*)d_in[0];
    const float* x_agg     = (const float*)d_in[1];
    const int*   c2a_src   = (const int*)d_in[2];
    const int*   c2a_dst   = (const int*)d_in[3];
    const int*   a2c_src   = (const int*)d_in[4];
    const int*   a2c_dst   = (const int*)d_in[5];
    const float* Wl_c2a    = (const float*)d_in[6];
    const float* Wr_c2a    = (const float*)d_in[7];
    const float* b_c2a     = (const float*)d_in[8];
    const float* Wl_a2c    = (const float*)d_in[9];
    const float* Wr_a2c    = (const float*)d_in[10];
    const float* b_a2c     = (const float*)d_in[11];
    const float* W_lin     = (const float*)d_in[12];
    const float* b_lin     = (const float*)d_in[13];
    float* out = (float*)d_out;

    void *p_xc0, *p_xc1, *p_xa0, *p_xa1, *p_Y, *p_mean, *p_Z;
    void *p_csr_c2a, *p_csr_a2c, *p_off_c2a, *p_off_a2c;
    void *p_cur_c2a, *p_cur_a2c, *p_cnt_c2a, *p_cnt_a2c, *p_invc_a, *p_invc_c;
    cudaGetSymbolAddress(&p_xc0, g_xc0);
    cudaGetSymbolAddress(&p_xc1, g_xc1);
    cudaGetSymbolAddress(&p_xa0, g_xa0);
    cudaGetSymbolAddress(&p_xa1, g_xa1);
    cudaGetSymbolAddress(&p_Y, g_Y);
    cudaGetSymbolAddress(&p_mean, g_mean_a);
    cudaGetSymbolAddress(&p_Z, g_Z);
    cudaGetSymbolAddress(&p_csr_c2a, g_csr_c2a);
    cudaGetSymbolAddress(&p_csr_a2c, g_csr_a2c);
    cudaGetSymbolAddress(&p_off_c2a, g_off_c2a);
    cudaGetSymbolAddress(&p_off_a2c, g_off_a2c);
    cudaGetSymbolAddress(&p_cur_c2a, g_cur_c2a);
    cudaGetSymbolAddress(&p_cur_a2c, g_cur_a2c);
    cudaGetSymbolAddress(&p_cnt_c2a, g_cnt_c2a);
    cudaGetSymbolAddress(&p_cnt_a2c, g_cnt_a2c);
    cudaGetSymbolAddress(&p_invc_a, g_invc_a);
    cudaGetSymbolAddress(&p_invc_c, g_invc_c);

    float* xcb[2] = {(float*)p_xc0, (float*)p_xc1};
    float* xab[2] = {(float*)p_xa0, (float*)p_xa1};

    // ---- CSR build (once per launch; edge lists are layer-invariant) ----
    zero_int_kernel<<<(N_AGG + 255) / 256, 256>>>((int*)p_cnt_c2a, N_AGG);
    zero_int_kernel<<<(N_CLI + 255) / 256, 256>>>((int*)p_cnt_a2c, N_CLI);
    hist_c2a_kernel<<<296, 256>>>(c2a_dst, (int*)p_cnt_c2a);
    hist_a2c_kernel<<<(NE + 255) / 256, 256>>>(a2c_dst, (int*)p_cnt_a2c);
    scan_init_kernel<<<1, 1024>>>((const int*)p_cnt_c2a, (int*)p_off_c2a,
                                  (int*)p_cur_c2a, (float*)p_invc_a, N_AGG);
    scan_init_kernel<<<1, 1024>>>((const int*)p_cnt_a2c, (int*)p_off_a2c,
                                  (int*)p_cur_a2c, (float*)p_invc_c, N_CLI);
    scatter_kernel<<<(NE + 255) / 256, 256>>>(c2a_src, c2a_dst, (int*)p_cur_c2a, (int*)p_csr_c2a);
    scatter_kernel<<<(NE + 255) / 256, 256>>>(a2c_src, a2c_dst, (int*)p_cur_a2c, (int*)p_csr_a2c);

    // ---- layers ----
    const float* xc_in = x_clients;
    const float* xa_in = x_agg;
    for (int l = 0; l < NLAY; l++) {
        const float* WlA = Wl_a2c + l * D * D;
        const float* WrA = Wr_a2c + l * D * D;
        const float* bA  = b_a2c + l * D;
        const float* WlC = Wl_c2a + l * D * D;
        const float* WrC = Wr_c2a + l * D * D;
        const float* bC  = b_c2a + l * D;
        float* xc_out = xcb[l & 1];
        float* xa_out = xab[l & 1];

        // a2c path: Y = xa @ Wl (fold Wl before gather), Z = xc @ Wr + b, then gather
        gemm_small_kernel<<<N_AGG, 128>>>(xa_in, WlA, (float*)p_Y);
        big_gemm_kernel<<<(N_CLI + BM - 1) / BM, 256>>>(xc_in, WrA, bA, (float*)p_Z, N_CLI);
        client_update_kernel<<<(N_CLI * 32 + 255) / 256, 256>>>(
            (const float*)p_Z, (const float*)p_Y, (const int*)p_csr_a2c,
            (const int*)p_off_a2c, (const float*)p_invc_c, xc_out);

        // c2a path (dead in last layer: final xa never used)
        if (l < NLAY - 1) {
            agg_c2a_kernel<<<N_AGG, 128>>>(xc_in, (const int*)p_csr_c2a,
                                           (const int*)p_off_c2a, (const float*)p_invc_a,
                                           (float*)p_mean);
            agg_update_kernel<<<N_AGG, 128>>>((const float*)p_mean, xa_in, WlC, WrC, bC, xa_out);
            xa_in = xa_out;
        }
        xc_in = xc_out;
    }

    final_kernel<<<(N_CLI * 32 + 255) / 256, 256>>>(xc_in, W_lin, b_lin, out);
}